// round 6
// baseline (speedup 1.0000x reference)
#include <cuda_runtime.h>
#include <cuda_fp16.h>
#include <math.h>
#include <stdint.h>

// Shapes (fixed)
#define HW_DIM  1024
#define C_DIM   256
#define N_TOK   32768
#define K_CODES 1024
#define Z_ELEMS 8388608
#define BETA_F  0.25f

// tiling: CTA = 128 tokens x 1024 codes, 16 superchunks of 64 codes
#define MT      128
#define SCH     64                 // codes per superchunk
#define NSUPER  (K_CODES / SCH)    // 16
#define KSTEPS  (C_DIM / 16)       // 16

// fp16 split scale
#define LO_S    2048.0f
#define LO_IS   4.8828125e-4f

// smem layout (bytes)
#define ROWB    528                // A row: 264 halves (528%128=16 -> ldsm clean)
#define BROWB   1040               // B row: code row, hi/lo interleaved per 16B
#define AH_OFF  0
#define AL_OFF  67584              // 128*528
#define B0_OFF  135168             // 32*1040 = 33280
#define B1_OFF  168448
#define NS_OFF  201728             // 1024 floats
#define CV_OFF  205824             // 128*2 floats
#define CI_OFF  206848             // 128*2 ints
#define KF_OFF  207872             // 128 ints
#define SMEM_TOTAL 208384

static __device__ int    g_counts[K_CODES];
static __device__ float  g_norms[K_CODES];
static __device__ float  g_partials[256];
// pre-split codebook, row = 1024B: per 8-k block [hi x8 | lo x8] halves
static __device__ __half g_cbi[K_CODES * 512];

// ---------------------------------------------------------------------------
__device__ __forceinline__ uint32_t smem_u32(const void* p) {
    uint32_t a;
    asm("{ .reg .u64 T; cvta.to.shared.u64 T, %1; cvt.u32.u64 %0, T; }"
        : "=r"(a) : "l"(p));
    return a;
}
__device__ __forceinline__ void ldsm4(uint32_t addr, uint32_t r[4]) {
    asm volatile("ldmatrix.sync.aligned.m8n8.x4.shared.b16 {%0,%1,%2,%3}, [%4];"
                 : "=r"(r[0]), "=r"(r[1]), "=r"(r[2]), "=r"(r[3]) : "r"(addr));
}
__device__ __forceinline__ void mma_f16(float c[4], const uint32_t a[4],
                                        uint32_t b0, uint32_t b1) {
    asm volatile(
        "mma.sync.aligned.m16n8k16.row.col.f32.f16.f16.f32 "
        "{%0,%1,%2,%3}, {%4,%5,%6,%7}, {%8,%9}, {%0,%1,%2,%3};"
        : "+f"(c[0]), "+f"(c[1]), "+f"(c[2]), "+f"(c[3])
        : "r"(a[0]), "r"(a[1]), "r"(a[2]), "r"(a[3]), "r"(b0), "r"(b1));
}
#define CP_ASYNC16(dst, src) \
    asm volatile("cp.async.cg.shared.global [%0], [%1], 16;" :: "r"(dst), "l"(src))
#define CP_COMMIT() asm volatile("cp.async.commit_group;" ::: "memory")
#define CP_WAIT0()  asm volatile("cp.async.wait_group 0;" ::: "memory")

__device__ __forceinline__ void split16(float a, __half& hi, __half& lo) {
    hi = __float2half_rn(a);
    lo = __float2half_rn((a - __half2float(hi)) * LO_S);
}

// ---------------------------------------------------------------------------
// prep: split codebook into interleaved hi/lo layout + norms + zero counts
__global__ void prep_kernel(const float* __restrict__ cb) {
    __shared__ float red[8];
    const int code = blockIdx.x;
    const int c    = threadIdx.x;
    float v = cb[code * C_DIM + c];
    __half hi, lo;
    split16(v, hi, lo);
    int base = code * 512 + (c >> 3) * 16 + (c & 7);
    g_cbi[base]     = hi;
    g_cbi[base + 8] = lo;
    float s = v * v;
    #pragma unroll
    for (int off = 16; off > 0; off >>= 1)
        s += __shfl_down_sync(0xffffffffu, s, off);
    if ((c & 31) == 0) red[c >> 5] = s;
    __syncthreads();
    if (c == 0) {
        float t = 0.f;
        #pragma unroll
        for (int i = 0; i < 8; i++) t += red[i];
        g_norms[code]  = t;
        g_counts[code] = 0;
    }
}

// ---------------------------------------------------------------------------
// fused split-fp16 GEMM-argmin + gather + loss partial.
// 8 warps = 4 token-groups x 2 code-groups; warp tile = 32 tok x 32 codes.
__global__ __launch_bounds__(256, 1)
void argmin_fused(const float* __restrict__ z, const float* __restrict__ cb,
                  float* __restrict__ out) {
    extern __shared__ char smem[];
    const uint32_t sb = smem_u32(smem);
    float* ns    = (float*)(smem + NS_OFF);
    float* candv = (float*)(smem + CV_OFF);
    int*   candi = (int*)(smem + CI_OFF);
    int*   kf    = (int*)(smem + KF_OFF);

    const int tid  = threadIdx.x;
    const int warp = tid >> 5;
    const int lane = tid & 31;
    const int tg   = warp & 3;       // token group (32 tokens)
    const int cg   = warp >> 2;      // code group: buf0 or buf1 (32 codes)
    const int g    = lane >> 2;
    const int t    = lane & 3;

    const int n0  = blockIdx.x * MT;
    const int b   = n0 >> 10;
    const int hw0 = n0 & 1023;
    const float* zb = z + (size_t)b * (C_DIM * HW_DIM) + hw0;

    // prefetch superchunk 0 (both buffers), 16 cp.async per thread
    auto prefetch = [&](int sc) {
        const char* src0 = (const char*)g_cbi + (size_t)sc * SCH * 1024;
        #pragma unroll
        for (int it = 0; it < 16; it++) {
            int i   = it * 256 + tid;
            int row = i >> 6;        // 0..63
            int seg = i & 63;
            uint32_t dst = (row < 32)
                ? sb + B0_OFF + (uint32_t)(row * BROWB + seg * 16)
                : sb + B1_OFF + (uint32_t)((row - 32) * BROWB + seg * 16);
            CP_ASYNC16(dst, src0 + (size_t)row * 1024 + seg * 16);
        }
    };
    prefetch(0); CP_COMMIT();

    // stage A (128 tok x 256 c) as fp16 hi/lo, coalesced over tokens
    for (int it = 0; it < 128; it++) {
        int i  = it * 256 + tid;
        int tk = i & 127;
        int c  = i >> 7;
        float a = zb[(size_t)c * HW_DIM + tk];
        __half hi, lo;
        split16(a, hi, lo);
        *(__half*)(smem + AH_OFF + tk * ROWB + c * 2) = hi;
        *(__half*)(smem + AL_OFF + tk * ROWB + c * 2) = lo;
    }
    #pragma unroll
    for (int it = 0; it < 4; it++) ns[it * 256 + tid] = g_norms[it * 256 + tid];

    // per-lane ldsm addresses
    const uint32_t aH = sb + AH_OFF + (uint32_t)((tg * 32 + (lane & 15)) * ROWB + (lane >> 4) * 16);
    const uint32_t aL = aH + (uint32_t)(AL_OFF - AH_OFF);
    // B: one ldsm4 -> [bh k0-7][bl k0-7][bh k8-15][bl k8-15] for an 8-code tile
    const uint32_t bB = sb + (cg ? B1_OFF : B0_OFF)
                      + (uint32_t)((lane & 7) * BROWB + (lane >> 3) * 16);

    float bestv4[4];
    int   besti4[4];
    #pragma unroll
    for (int s = 0; s < 4; s++) { bestv4[s] = 3.4e38f; besti4[s] = 0; }

    for (int sc = 0; sc < NSUPER; sc++) {
        CP_WAIT0();
        __syncthreads();             // buffers + (sc==0) A staging visible

        float hh[2][4][4], md[2][4][4];
        #pragma unroll
        for (int mt = 0; mt < 2; mt++)
            #pragma unroll
            for (int nb = 0; nb < 4; nb++)
                #pragma unroll
                for (int q = 0; q < 4; q++) { hh[mt][nb][q] = 0.f; md[mt][nb][q] = 0.f; }

        #pragma unroll 4
        for (int ks = 0; ks < KSTEPS; ks++) {
            uint32_t ah[2][4], al[2][4];
            #pragma unroll
            for (int mt = 0; mt < 2; mt++) {
                ldsm4(aH + (uint32_t)(mt * 16 * ROWB + ks * 32), ah[mt]);
                ldsm4(aL + (uint32_t)(mt * 16 * ROWB + ks * 32), al[mt]);
            }
            #pragma unroll
            for (int nb = 0; nb < 4; nb++) {
                uint32_t bb[4];
                ldsm4(bB + (uint32_t)(nb * (8 * BROWB) + ks * 64), bb);
                #pragma unroll
                for (int mt = 0; mt < 2; mt++) {
                    mma_f16(hh[mt][nb], ah[mt], bb[0], bb[2]);   // hi*hi
                    mma_f16(md[mt][nb], ah[mt], bb[1], bb[3]);   // hi*lo
                    mma_f16(md[mt][nb], al[mt], bb[0], bb[2]);   // lo*hi
                }
            }
        }

        __syncthreads();             // all reads done before refill
        if (sc + 1 < NSUPER) { prefetch(sc + 1); CP_COMMIT(); }

        // epilogue overlaps the async loads
        #pragma unroll
        for (int nb = 0; nb < 4; nb++) {
            int cl = cg * 32 + nb * 8 + 2 * t;
            int code0 = sc * SCH + cl;
            float nk0 = ns[code0];
            float nk1 = ns[code0 + 1];
            #pragma unroll
            for (int mt = 0; mt < 2; mt++) {
                float d00 = nk0 - 2.f * (hh[mt][nb][0] + md[mt][nb][0] * LO_IS);
                float d01 = nk1 - 2.f * (hh[mt][nb][1] + md[mt][nb][1] * LO_IS);
                float d10 = nk0 - 2.f * (hh[mt][nb][2] + md[mt][nb][2] * LO_IS);
                float d11 = nk1 - 2.f * (hh[mt][nb][3] + md[mt][nb][3] * LO_IS);
                int s0 = mt * 2, s1 = mt * 2 + 1;
                if (d00 < bestv4[s0]) { bestv4[s0] = d00; besti4[s0] = code0; }
                if (d01 < bestv4[s0]) { bestv4[s0] = d01; besti4[s0] = code0 + 1; }
                if (d10 < bestv4[s1]) { bestv4[s1] = d10; besti4[s1] = code0; }
                if (d11 < bestv4[s1]) { bestv4[s1] = d11; besti4[s1] = code0 + 1; }
            }
        }
    }

    // lane-reduce across t (lanes 4g..4g+3 share a token row)
    #pragma unroll
    for (int s = 0; s < 4; s++) {
        #pragma unroll
        for (int m = 1; m <= 2; m <<= 1) {
            float v2 = __shfl_xor_sync(0xffffffffu, bestv4[s], m);
            int   i2 = __shfl_xor_sync(0xffffffffu, besti4[s], m);
            if (v2 < bestv4[s] || (v2 == bestv4[s] && i2 < besti4[s])) {
                bestv4[s] = v2; besti4[s] = i2;
            }
        }
    }
    if (t == 0) {
        #pragma unroll
        for (int s = 0; s < 4; s++) {
            int mt = s >> 1, h = s & 1;
            int tok = tg * 32 + mt * 16 + h * 8 + g;
            candv[tok * 2 + cg] = bestv4[s];
            candi[tok * 2 + cg] = besti4[s];
        }
    }
    __syncthreads();
    if (tid < MT) {
        float v0 = candv[tid * 2], v1 = candv[tid * 2 + 1];
        int   i0 = candi[tid * 2], i1 = candi[tid * 2 + 1];
        int bi;
        if (v1 < v0 || (v1 == v0 && i1 < i0)) bi = i1; else bi = i0;
        kf[tid] = bi;
        atomicAdd(&g_counts[bi], 1);
    }
    __syncthreads();

    // -------- fused gather + loss: this CTA's 128 tokens x 256 channels ----
    {
        const int tok = tid & 127;
        const int ch0 = (tid >> 7) * 128;          // channels [ch0, ch0+128)
        const int k   = kf[tok];
        const float4* crow = (const float4*)(cb + (size_t)k * C_DIM + ch0);
        const float* zp = zb + (size_t)ch0 * HW_DIM + tok;
        float*       op = out + (size_t)b * (C_DIM * HW_DIM) + hw0
                              + (size_t)ch0 * HW_DIM + tok;
        float s = 0.f;
        #pragma unroll 8
        for (int j = 0; j < 32; j++) {
            float4 e = crow[j];
            int c = j * 4;
            float d0 = e.x - zp[(c + 0) * HW_DIM];
            float d1 = e.y - zp[(c + 1) * HW_DIM];
            float d2 = e.z - zp[(c + 2) * HW_DIM];
            float d3 = e.w - zp[(c + 3) * HW_DIM];
            s += d0 * d0 + d1 * d1 + d2 * d2 + d3 * d3;
            op[(c + 0) * HW_DIM] = e.x;
            op[(c + 1) * HW_DIM] = e.y;
            op[(c + 2) * HW_DIM] = e.z;
            op[(c + 3) * HW_DIM] = e.w;
        }
        // block reduction (deterministic fixed tree) reusing candv area
        float* red = candv;                        // 256 floats available
        red[tid] = s;
        __syncthreads();
        for (int off = 128; off > 0; off >>= 1) {
            if (tid < off) red[tid] += red[tid + off];
            __syncthreads();
        }
        if (tid == 0) g_partials[blockIdx.x] = red[0];
    }
}

// ---------------------------------------------------------------------------
__global__ void finalize_kernel(float* __restrict__ out, int out_size) {
    __shared__ float s1[1024];
    __shared__ float s2[1024];
    const int tid = threadIdx.x;
    float ls = (tid < 256) ? g_partials[tid] : 0.f;
    float p  = (float)g_counts[tid] * (1.0f / (float)N_TOK);
    float pc = fmaxf(p, 1e-10f);
    s1[tid] = ls;
    s2[tid] = pc * logf(pc);
    __syncthreads();
    for (int off = 512; off > 0; off >>= 1) {
        if (tid < off) { s1[tid] += s1[tid + off]; s2[tid] += s2[tid + off]; }
        __syncthreads();
    }
    if (tid == 0) {
        float mse = s1[0] * (1.0f / (float)Z_ELEMS);
        if (out_size >= Z_ELEMS + 1) out[Z_ELEMS]     = mse * (1.0f + BETA_F);
        if (out_size >= Z_ELEMS + 2) out[Z_ELEMS + 1] = expf(-s2[0]);
    }
}

// ---------------------------------------------------------------------------
extern "C" void kernel_launch(void* const* d_in, const int* in_sizes, int n_in,
                              void* d_out, int out_size) {
    const float* z  = (const float*)d_in[0];
    const float* cb = (const float*)d_in[1];
    float* out = (float*)d_out;

    cudaFuncSetAttribute(argmin_fused,
                         cudaFuncAttributeMaxDynamicSharedMemorySize, SMEM_TOTAL);

    prep_kernel<<<K_CODES, 256>>>(cb);
    argmin_fused<<<N_TOK / MT, 256, SMEM_TOTAL>>>(z, cb, out);
    finalize_kernel<<<1, 1024>>>(out, out_size);
}